// round 1
// baseline (speedup 1.0000x reference)
#include <cuda_runtime.h>
#include <math.h>

// ---------------------------------------------------------------------------
// Problem constants (fixed by the reference)
// ---------------------------------------------------------------------------
namespace {
constexpr int Dh  = 512;        // hidden dim
constexpr int Bn  = 256;        // batch
constexpr int Rn  = 196;        // image regions
constexpr int Tn  = 26;         // sequence length
constexpr int AVn = 3000;       // answer vocab
constexpr int Mw  = Bn * Tn;    // 6656 token rows
constexpr int Nbig = 7 * Dh;    // 3584 (7 conv blocks)
constexpr int Ng   = 4 * Dh;    // 2048 (lstm gates)
}

// ---------------------------------------------------------------------------
// Scratch (static __device__ arrays — no allocation anywhere)
// ---------------------------------------------------------------------------
__device__ float g_Simg   [Bn * Dh];              // sum_r image_feat
__device__ float g_imgproj[Bn * Dh];              // sum_r (img @ W_ip + b_ip)
__device__ float g_word   [(size_t)Mw * Dh];      // gathered embeddings
__device__ float g_Wbig   [(size_t)Dh * Nbig];    // assembled conv weights
__device__ float g_P7     [(size_t)Mw * Nbig];    // word @ Wbig
__device__ float g_phrase [(size_t)Mw * Dh];
__device__ float g_xg     [(size_t)Mw * Ng];      // phrase @ Wx + b
__device__ float g_hA     [Bn * Dh];
__device__ float g_hB     [Bn * Dh];
__device__ float g_cst    [Bn * Dh];
__device__ float g_hsum   [Bn * Dh];
__device__ float g_vecA   [Bn * Dh];
__device__ float g_vecB   [Bn * Dh];
__device__ float g_cat    [Bn * 2 * Dh];
__device__ float g_hw     [Bn * Dh];
__device__ float g_hp     [Bn * Dh];
__device__ float g_hs     [Bn * Dh];

__device__ __forceinline__ float sigf(float x) { return 1.0f / (1.0f + expf(-x)); }

// ---------------------------------------------------------------------------
// 1. Assemble Wbig [512, 3584]: 7 column blocks of 512
//    0: uni(cur)  1: bi(prev half) 2: bi(cur) 3: bi(next half)
//    4: tri(prev) 5: tri(cur)      6: tri(next)
// ---------------------------------------------------------------------------
__global__ void k_build_wbig(const float* __restrict__ Wu,
                             const float* __restrict__ Wb,
                             const float* __restrict__ Wt) {
    int idx = blockIdx.x * 256 + threadIdx.x;
    if (idx >= Dh * Nbig) return;
    int k = idx / Nbig;
    int n = idx % Nbig;
    int blk = n >> 9;           // /512
    int o   = n & 511;
    float v;
    switch (blk) {
        case 0:  v = Wu[(size_t)k * Dh + o];                            break;
        case 1:  v = (k >= 256) ? Wb[(size_t)(k - 256) * Dh + o] : 0.f; break;
        case 2:  v = Wb[(size_t)(k + 256) * Dh + o];                    break;
        case 3:  v = (k < 256) ? Wb[(size_t)(k + 768) * Dh + o] : 0.f;  break;
        case 4:  v = Wt[(size_t)k * Dh + o];                            break;
        case 5:  v = Wt[(size_t)(k + 512) * Dh + o];                    break;
        default: v = Wt[(size_t)(k + 1024) * Dh + o];                   break;
    }
    g_Wbig[idx] = v;
}

// ---------------------------------------------------------------------------
// 2. sum image_feat over R  -> g_Simg [B, D]
// ---------------------------------------------------------------------------
__global__ void k_sum_image(const float* __restrict__ img) {
    int d = blockIdx.x * 256 + threadIdx.x;   // 0..511
    int b = blockIdx.y;
    const float* p = img + (size_t)b * Rn * Dh + d;
    float s = 0.f;
    #pragma unroll 4
    for (int r = 0; r < Rn; r++) s += p[(size_t)r * Dh];
    g_Simg[b * Dh + d] = s;
}

// ---------------------------------------------------------------------------
// 3. gather embeddings: word[m,:] = emb[q[m],:]
// ---------------------------------------------------------------------------
__global__ void k_gather(const float* __restrict__ emb, const int* __restrict__ q) {
    int m  = blockIdx.x;
    int qi = q[m];
    const float4* src = (const float4*)(emb + (size_t)qi * Dh);
    float4*       dst = (float4*)(g_word + (size_t)m * Dh);
    dst[threadIdx.x] = src[threadIdx.x];      // 128 threads * float4 = 512
}

// ---------------------------------------------------------------------------
// Generic tiled fp32 GEMM: C[M,N] = A[M,K] @ B[K,N] (+ bscale*bias) (+tanh)
// EPI: 0 = none, 1 = bias, 2 = bias + tanh
// ---------------------------------------------------------------------------
template <int BM, int BN, int BK, int TM, int TN, int EPI>
__global__ void sgemm(const float* __restrict__ A, const float* __restrict__ Bw,
                      float* __restrict__ C, const float* __restrict__ bias,
                      float bscale, int M, int N, int K) {
    constexpr int THREADS = (BM / TM) * (BN / TN);
    __shared__ float As[BK][BM];
    __shared__ float Bs[BK][BN];

    const int tid  = threadIdx.x;
    const int ntx  = BN / TN;
    const int tx   = tid % ntx;
    const int ty   = tid / ntx;
    const int row0 = blockIdx.y * BM;
    const int col0 = blockIdx.x * BN;

    float acc[TM][TN];
    #pragma unroll
    for (int i = 0; i < TM; i++)
        #pragma unroll
        for (int j = 0; j < TN; j++) acc[i][j] = 0.f;

    for (int k0 = 0; k0 < K; k0 += BK) {
        constexpr int AI = (BM * BK) / THREADS;
        #pragma unroll
        for (int it = 0; it < AI; it++) {
            int i = tid + it * THREADS;
            int m = i / BK, k = i % BK;
            int gm = row0 + m;
            As[k][m] = (gm < M) ? A[(size_t)gm * K + k0 + k] : 0.f;
        }
        constexpr int BI = (BK * BN) / THREADS;
        #pragma unroll
        for (int it = 0; it < BI; it++) {
            int i = tid + it * THREADS;
            int k = i / BN, n = i % BN;
            int gn = col0 + n;
            Bs[k][n] = (gn < N) ? Bw[(size_t)(k0 + k) * N + gn] : 0.f;
        }
        __syncthreads();
        #pragma unroll
        for (int k = 0; k < BK; k++) {
            float a[TM], bv[TN];
            #pragma unroll
            for (int i = 0; i < TM; i++) a[i] = As[k][ty * TM + i];
            #pragma unroll
            for (int j = 0; j < TN; j++) bv[j] = Bs[k][tx * TN + j];
            #pragma unroll
            for (int i = 0; i < TM; i++)
                #pragma unroll
                for (int j = 0; j < TN; j++)
                    acc[i][j] = fmaf(a[i], bv[j], acc[i][j]);
        }
        __syncthreads();
    }

    #pragma unroll
    for (int i = 0; i < TM; i++) {
        int gm = row0 + ty * TM + i;
        if (gm >= M) continue;
        #pragma unroll
        for (int j = 0; j < TN; j++) {
            int gn = col0 + tx * TN + j;
            if (gn >= N) continue;
            float v = acc[i][j];
            if (EPI >= 1) v += bscale * bias[gn];
            if (EPI == 2) v = tanhf(v);
            C[(size_t)gm * N + gn] = v;
        }
    }
}

// ---------------------------------------------------------------------------
// 5. phrase = max(uni, bi, tri) from P7 with neighbor shifts + biases
// ---------------------------------------------------------------------------
__global__ void k_phrase(const float* __restrict__ b_uni,
                         const float* __restrict__ b_bi,
                         const float* __restrict__ b_tri) {
    int m = blockIdx.x;          // 0..Mw-1
    int d = threadIdx.x;         // 0..511
    int t = m % Tn;
    const float* P = g_P7 + (size_t)m * Nbig;
    float uni = P[d]        + b_uni[d];
    float bi  = P[1024 + d] + b_bi[d];
    float tri = P[2560 + d] + b_tri[d];
    if (t > 0) {
        const float* Pm = P - Nbig;
        bi  += Pm[512 + d];
        tri += Pm[2048 + d];
    }
    if (t < Tn - 1) {
        const float* Pp = P + Nbig;
        bi  += Pp[1536 + d];
        tri += Pp[3072 + d];
    }
    g_phrase[(size_t)m * Dh + d] = fmaxf(uni, fmaxf(bi, tri));
}

// ---------------------------------------------------------------------------
// LSTM: zero state, then 26 fused (h@Wh + gates) steps, accumulating hsum
// ---------------------------------------------------------------------------
__global__ void k_zero_state() {
    int i = blockIdx.x * 256 + threadIdx.x;
    if (i < Bn * Dh) { g_hA[i] = 0.f; g_cst[i] = 0.f; g_hsum[i] = 0.f; }
}

__global__ void k_lstm_step(const float* __restrict__ hin,
                            float* __restrict__ hout,
                            const float* __restrict__ Wh, int t) {
    // grid: (Dh/32, Bn/32), 256 threads (16 tx x 16 ty)
    __shared__ float Hs[16][32];     // [k][b_local]
    __shared__ float Ws[16][128];    // [k][gate*32 + d_local]
    const int tid = threadIdx.x;
    const int tx  = tid % 16;
    const int ty  = tid / 16;
    const int d0  = blockIdx.x * 32;
    const int b0  = blockIdx.y * 32;

    float acc[2][4][2];
    #pragma unroll
    for (int i = 0; i < 2; i++)
        #pragma unroll
        for (int g = 0; g < 4; g++)
            #pragma unroll
            for (int j = 0; j < 2; j++) acc[i][g][j] = 0.f;

    for (int k0 = 0; k0 < Dh; k0 += 16) {
        #pragma unroll
        for (int it = 0; it < 2; it++) {            // 512 / 256
            int i = tid + it * 256;
            int bl = i / 16, k = i % 16;
            Hs[k][bl] = hin[(size_t)(b0 + bl) * Dh + k0 + k];
        }
        #pragma unroll
        for (int it = 0; it < 8; it++) {            // 2048 / 256
            int i = tid + it * 256;
            int k = i / 128, c = i % 128;
            int g = c / 32, dl = c % 32;
            Ws[k][c] = Wh[(size_t)(k0 + k) * Ng + g * Dh + d0 + dl];
        }
        __syncthreads();
        #pragma unroll
        for (int k = 0; k < 16; k++) {
            float a0 = Hs[k][ty * 2];
            float a1 = Hs[k][ty * 2 + 1];
            #pragma unroll
            for (int g = 0; g < 4; g++) {
                float w0 = Ws[k][g * 32 + tx * 2];
                float w1 = Ws[k][g * 32 + tx * 2 + 1];
                acc[0][g][0] = fmaf(a0, w0, acc[0][g][0]);
                acc[0][g][1] = fmaf(a0, w1, acc[0][g][1]);
                acc[1][g][0] = fmaf(a1, w0, acc[1][g][0]);
                acc[1][g][1] = fmaf(a1, w1, acc[1][g][1]);
            }
        }
        __syncthreads();
    }

    #pragma unroll
    for (int i = 0; i < 2; i++) {
        int b = b0 + ty * 2 + i;
        size_t xrow = ((size_t)b * Tn + t) * Ng;
        #pragma unroll
        for (int j = 0; j < 2; j++) {
            int d = d0 + tx * 2 + j;
            float gi = acc[i][0][j] + g_xg[xrow + d];
            float gf = acc[i][1][j] + g_xg[xrow + Dh + d];
            float gc = acc[i][2][j] + g_xg[xrow + 2 * Dh + d];
            float go = acc[i][3][j] + g_xg[xrow + 3 * Dh + d];
            size_t bd = (size_t)b * Dh + d;
            float c = sigf(gf) * g_cst[bd] + sigf(gi) * tanhf(gc);
            g_cst[bd] = c;
            float h = sigf(go) * tanhf(c);
            hout[bd] = h;
            g_hsum[bd] += h;
        }
    }
}

// ---------------------------------------------------------------------------
// small elementwise helpers
// ---------------------------------------------------------------------------
__global__ void k_sum_t(const float* __restrict__ X, float* __restrict__ out) {
    int d = blockIdx.x * 256 + threadIdx.x;
    int b = blockIdx.y;
    float s = 0.f;
    #pragma unroll
    for (int t = 0; t < Tn; t++) s += X[((size_t)b * Tn + t) * Dh + d];
    out[b * Dh + d] = s;
}

__global__ void k_add(const float* __restrict__ x, const float* __restrict__ y,
                      float* __restrict__ out) {
    int i = blockIdx.x * 256 + threadIdx.x;
    if (i < Bn * Dh) out[i] = x[i] + y[i];
}

__global__ void k_concat(const float* __restrict__ x, const float* __restrict__ y,
                         float* __restrict__ cat) {
    int i = blockIdx.x * 256 + threadIdx.x;
    if (i >= Bn * Dh) return;
    int b = i / Dh, d = i % Dh;
    cat[(size_t)b * 2 * Dh + d]      = x[i];
    cat[(size_t)b * 2 * Dh + Dh + d] = y[i];
}

// ---------------------------------------------------------------------------
// Launch
// ---------------------------------------------------------------------------
extern "C" void kernel_launch(void* const* d_in, const int* in_sizes, int n_in,
                              void* d_out, int out_size) {
    const float* image_feat = (const float*)d_in[0];
    const int*   qenc       = (const int*)d_in[1];
    const float* W_ip = (const float*)d_in[2];  const float* b_ip = (const float*)d_in[3];
    const float* emb  = (const float*)d_in[4];
    const float* W_uni = (const float*)d_in[5]; const float* b_uni = (const float*)d_in[6];
    const float* W_bi  = (const float*)d_in[7]; const float* b_bi  = (const float*)d_in[8];
    const float* W_tri = (const float*)d_in[9]; const float* b_tri = (const float*)d_in[10];
    const float* Wx = (const float*)d_in[11];   const float* Wh = (const float*)d_in[12];
    const float* b_lstm = (const float*)d_in[13];
    // d_in[14..23] (W_c/b_c/W_v/b_v/W_q/b_q/W_ai/b_ai/W_at/b_at) are provably unused:
    // _pool's softmax is over a size-1 axis -> weights are identically 1.
    const float* W_w = (const float*)d_in[24];  const float* b_w = (const float*)d_in[25];
    const float* W_p = (const float*)d_in[26];  const float* b_p = (const float*)d_in[27];
    const float* W_s = (const float*)d_in[28];  const float* b_s = (const float*)d_in[29];
    const float* W_f = (const float*)d_in[30];  const float* b_f = (const float*)d_in[31];
    float* out = (float*)d_out;

    float *Simg, *imgproj, *word, *phrase, *xg, *hA, *hB, *hsum;
    float *vecA, *vecB, *cat, *hw, *hp, *hs, *P7, *Wbig;
    cudaGetSymbolAddress((void**)&Simg,    g_Simg);
    cudaGetSymbolAddress((void**)&imgproj, g_imgproj);
    cudaGetSymbolAddress((void**)&word,    g_word);
    cudaGetSymbolAddress((void**)&Wbig,    g_Wbig);
    cudaGetSymbolAddress((void**)&P7,      g_P7);
    cudaGetSymbolAddress((void**)&phrase,  g_phrase);
    cudaGetSymbolAddress((void**)&xg,      g_xg);
    cudaGetSymbolAddress((void**)&hA,      g_hA);
    cudaGetSymbolAddress((void**)&hB,      g_hB);
    cudaGetSymbolAddress((void**)&hsum,    g_hsum);
    cudaGetSymbolAddress((void**)&vecA,    g_vecA);
    cudaGetSymbolAddress((void**)&vecB,    g_vecB);
    cudaGetSymbolAddress((void**)&cat,     g_cat);
    cudaGetSymbolAddress((void**)&hw,      g_hw);
    cudaGetSymbolAddress((void**)&hp,      g_hp);
    cudaGetSymbolAddress((void**)&hs,      g_hs);

    // 1. assemble n-gram conv weights
    k_build_wbig<<<(Dh * Nbig + 255) / 256, 256>>>(W_uni, W_bi, W_tri);
    // 2. image sum + projection:  imgproj = (sum_r x) @ W_ip + R*b_ip
    k_sum_image<<<dim3(2, Bn), 256>>>(image_feat);
    sgemm<64, 64, 8, 4, 4, 1><<<dim3(Dh / 64, Bn / 64), 256>>>(
        Simg, W_ip, imgproj, b_ip, (float)Rn, Bn, Dh, Dh);
    // 3. embedding gather
    k_gather<<<Mw, 128>>>(emb, qenc);
    // 4. word @ Wbig -> P7   [6656, 3584]
    sgemm<128, 128, 8, 8, 8, 0><<<dim3(Nbig / 128, Mw / 128), 256>>>(
        word, Wbig, P7, nullptr, 0.f, Mw, Nbig, Dh);
    // 5. phrase = max(uni, bi, tri)
    k_phrase<<<Mw, Dh>>>(b_uni, b_bi, b_tri);
    // 6. xg = phrase @ Wx + b_lstm   [6656, 2048]
    sgemm<128, 128, 8, 8, 8, 1><<<dim3(Ng / 128, Mw / 128), 256>>>(
        phrase, Wx, xg, b_lstm, 1.f, Mw, Ng, Dh);
    // 7. LSTM recurrence (ping-pong h), accumulate hsum
    k_zero_state<<<(Bn * Dh + 255) / 256, 256>>>();
    for (int t = 0; t < Tn; t++) {
        const float* hi = (t & 1) ? hB : hA;
        float*       ho = (t & 1) ? hA : hB;
        k_lstm_step<<<dim3(Dh / 32, Bn / 32), 256>>>(hi, ho, Wh, t);
    }
    // 8. word level: h_w = tanh((imgsum + wordsum) @ W_w + b_w)
    k_sum_t<<<dim3(2, Bn), 256>>>(word, vecB);
    k_add<<<(Bn * Dh + 255) / 256, 256>>>(imgproj, vecB, vecA);
    sgemm<64, 64, 8, 4, 4, 2><<<dim3(Dh / 64, Bn / 64), 256>>>(
        vecA, W_w, hw, b_w, 1.f, Bn, Dh, Dh);
    // 9. phrase level: h_p = tanh(concat(imgsum + phrasesum, h_w) @ W_p + b_p)
    k_sum_t<<<dim3(2, Bn), 256>>>(phrase, vecB);
    k_add<<<(Bn * Dh + 255) / 256, 256>>>(imgproj, vecB, vecA);
    k_concat<<<(Bn * Dh + 255) / 256, 256>>>(vecA, hw, cat);
    sgemm<64, 64, 8, 4, 4, 2><<<dim3(Dh / 64, Bn / 64), 256>>>(
        cat, W_p, hp, b_p, 1.f, Bn, Dh, 2 * Dh);
    // 10. sentence level: h_s = tanh(concat(imgsum + hsum, h_p) @ W_s + b_s)
    k_add<<<(Bn * Dh + 255) / 256, 256>>>(imgproj, hsum, vecA);
    k_concat<<<(Bn * Dh + 255) / 256, 256>>>(vecA, hp, cat);
    sgemm<64, 64, 8, 4, 4, 2><<<dim3(Dh / 64, Bn / 64), 256>>>(
        cat, W_s, hs, b_s, 1.f, Bn, Dh, 2 * Dh);
    // 11. logits = h_s @ W_f + b_f   [256, 3000]
    sgemm<64, 64, 8, 4, 4, 1><<<dim3((AVn + 63) / 64, Bn / 64), 256>>>(
        hs, W_f, out, b_f, 1.f, Bn, AVn, Dh);
}

// round 4
// speedup vs baseline: 1.4252x; 1.4252x over previous
#include <cuda_runtime.h>
#include <cuda_bf16.h>
#include <cstdint>
#include <math.h>

// ---------------------------------------------------------------------------
// Problem constants
// ---------------------------------------------------------------------------
namespace {
constexpr int Dh  = 512;
constexpr int Bn  = 256;
constexpr int Rn  = 196;
constexpr int Tn  = 26;
constexpr int AVn = 3000;
constexpr int AVp = 3072;        // padded answer vocab (multiple of 128)
constexpr int Mw  = Bn * Tn;     // 6656
constexpr int Nbig = 7 * Dh;     // 3584
constexpr int Ng   = 4 * Dh;     // 2048
}

// ---------------------------------------------------------------------------
// Scratch (__device__ globals, no allocation anywhere)
// ---------------------------------------------------------------------------
__device__ float g_Simg   [Bn * Dh];
__device__ float g_imgproj[Bn * Dh];
__device__ float g_word   [(size_t)Mw * Dh];
__device__ float g_P7     [(size_t)Mw * Nbig];
__device__ float g_phrase [(size_t)Mw * Dh];
__device__ float g_xg     [(size_t)Mw * Ng];
__device__ float g_hA     [Bn * Dh];
__device__ float g_hB     [Bn * Dh];
__device__ float g_cst    [Bn * Dh];
__device__ float g_hsum   [Bn * Dh];
__device__ float g_hw     [Bn * Dh];
__device__ float g_hp     [Bn * Dh];
__device__ float g_hs     [Bn * Dh];

// bf16 hi/lo operand buffers
__device__ __nv_bfloat16 g_word_h[(size_t)Mw * Dh],  g_word_l[(size_t)Mw * Dh];
__device__ __nv_bfloat16 g_phr_h [(size_t)Mw * Dh],  g_phr_l [(size_t)Mw * Dh];
__device__ __nv_bfloat16 g_wbig_h[(size_t)Nbig * Dh],g_wbig_l[(size_t)Nbig * Dh];
__device__ __nv_bfloat16 g_wx_h  [(size_t)Ng * Dh],  g_wx_l  [(size_t)Ng * Dh];
__device__ __nv_bfloat16 g_wip_h [Dh * Dh],          g_wip_l [Dh * Dh];
__device__ __nv_bfloat16 g_ww_h  [Dh * Dh],          g_ww_l  [Dh * Dh];
__device__ __nv_bfloat16 g_wp_h  [Dh * 2 * Dh],      g_wp_l  [Dh * 2 * Dh];
__device__ __nv_bfloat16 g_ws_h  [Dh * 2 * Dh],      g_ws_l  [Dh * 2 * Dh];
__device__ __nv_bfloat16 g_wf_h  [(size_t)AVp * Dh], g_wf_l  [(size_t)AVp * Dh];
__device__ __nv_bfloat16 g_a512_h[Bn * Dh],          g_a512_l[Bn * Dh];
__device__ __nv_bfloat16 g_a1k_h [Bn * 2 * Dh],      g_a1k_l [Bn * 2 * Dh];

__device__ __forceinline__ float sigf(float x) { return 1.0f / (1.0f + expf(-x)); }
__device__ __forceinline__ void split_bf16(float x, __nv_bfloat16& h, __nv_bfloat16& l) {
    h = __float2bfloat16(x);
    l = __float2bfloat16(x - __bfloat162float(h));
}

// ---------------------------------------------------------------------------
// mma.sync helpers (sm_80-era PTX; runs on Blackwell tensor cores)
// ---------------------------------------------------------------------------
__device__ __forceinline__ uint32_t smem_u32(const void* p) {
    uint32_t a;
    asm("{ .reg .u64 t; cvta.to.shared.u64 t, %1; cvt.u32.u64 %0, t; }"
        : "=r"(a) : "l"(p));
    return a;
}

__device__ __forceinline__ void ldsm_x4(uint32_t& r0, uint32_t& r1,
                                        uint32_t& r2, uint32_t& r3, uint32_t a) {
    asm volatile("ldmatrix.sync.aligned.m8n8.x4.shared.b16 {%0,%1,%2,%3}, [%4];"
                 : "=r"(r0), "=r"(r1), "=r"(r2), "=r"(r3) : "r"(a));
}
__device__ __forceinline__ void ldsm_x2(uint32_t& r0, uint32_t& r1, uint32_t a) {
    asm volatile("ldmatrix.sync.aligned.m8n8.x2.shared.b16 {%0,%1}, [%2];"
                 : "=r"(r0), "=r"(r1) : "r"(a));
}
__device__ __forceinline__ void mma16816(float* c, const uint32_t* a, const uint32_t* b) {
    asm volatile(
        "mma.sync.aligned.m16n8k16.row.col.f32.bf16.bf16.f32 "
        "{%0,%1,%2,%3}, {%4,%5,%6,%7}, {%8,%9}, {%0,%1,%2,%3};"
        : "+f"(c[0]), "+f"(c[1]), "+f"(c[2]), "+f"(c[3])
        : "r"(a[0]), "r"(a[1]), "r"(a[2]), "r"(a[3]), "r"(b[0]), "r"(b[1]));
}
__device__ __forceinline__ void cp16(uint32_t saddr, const void* g) {
    asm volatile("cp.async.cg.shared.global [%0], [%1], 16;" :: "r"(saddr), "l"(g));
}
__device__ __forceinline__ void cp_commit() {
    asm volatile("cp.async.commit_group;");
}
template <int N> __device__ __forceinline__ void cp_wait() {
    asm volatile("cp.async.wait_group %0;" :: "n"(N));
}

// ---------------------------------------------------------------------------
// bf16x3 mma.sync GEMM: C[M,N] = A[M,K] @ B^T  (B stored [Npad][K] K-major)
// 128x128 block, 8 warps (2x4), warp tile 64x32, BK=32, cp.async double buffer.
// EPI: 0 none, 1 +bscale*bias, 2 tanh(x + bias)
// ---------------------------------------------------------------------------
namespace {
constexpr int BK      = 32;
constexpr int LDS_    = BK + 8;                 // 40 elems -> 80B rows (16B aligned)
constexpr int ARR_SZ  = 128 * LDS_;             // elems per operand array
constexpr int STAGE_E = 4 * ARR_SZ;             // Ah, Al, Bh, Bl
constexpr int GEMM_SMEM = 2 * STAGE_E * 2;      // bytes (2 stages, bf16)
}

template <int EPI>
__global__ __launch_bounds__(256) void gemm_t(
    const __nv_bfloat16* __restrict__ Ah, const __nv_bfloat16* __restrict__ Al,
    const __nv_bfloat16* __restrict__ Bh, const __nv_bfloat16* __restrict__ Bl,
    float* __restrict__ C, const float* __restrict__ bias, float bscale,
    int M, int N, int K)
{
    extern __shared__ __nv_bfloat16 smem[];
    const int tid  = threadIdx.x;
    const int lane = tid & 31;
    const int wid  = tid >> 5;
    const int wm   = wid & 1;          // 2 warps in M
    const int wn   = wid >> 1;         // 4 warps in N
    const int row0 = blockIdx.y * 128;
    const int col0 = blockIdx.x * 128;

    const __nv_bfloat16* srcs[4] = {Ah, Al, Bh, Bl};
    const int bases[4] = {row0, row0, col0, col0};

    // async stage loader: 4 arrays x 128 rows x 32 cols; 16B chunks
    auto load_stage = [&](int stage, int k0) {
        __nv_bfloat16* st = smem + stage * STAGE_E;
        #pragma unroll
        for (int j = 0; j < 4; j++) {
            #pragma unroll
            for (int p = 0; p < 2; p++) {
                int chunk = tid + p * 256;            // 0..511
                int r = chunk >> 2;
                int c = chunk & 3;
                uint32_t sa = smem_u32(st + j * ARR_SZ + r * LDS_ + c * 8);
                cp16(sa, srcs[j] + (size_t)(bases[j] + r) * K + k0 + c * 8);
            }
        }
        cp_commit();
    };

    float acc[4][4][4];
    #pragma unroll
    for (int i = 0; i < 4; i++)
        #pragma unroll
        for (int j = 0; j < 4; j++)
            #pragma unroll
            for (int q = 0; q < 4; q++) acc[i][j][q] = 0.f;

    const int nkt = K / BK;
    load_stage(0, 0);

    for (int kt = 0; kt < nkt; kt++) {
        if (kt + 1 < nkt) {
            load_stage((kt + 1) & 1, (kt + 1) * BK);
            cp_wait<1>();
        } else {
            cp_wait<0>();
        }
        __syncthreads();

        __nv_bfloat16* st = smem + (kt & 1) * STAGE_E;
        __nv_bfloat16* sAh = st;
        __nv_bfloat16* sAl = st + ARR_SZ;
        __nv_bfloat16* sBh = st + 2 * ARR_SZ;
        __nv_bfloat16* sBl = st + 3 * ARR_SZ;

        #pragma unroll
        for (int ks = 0; ks < BK; ks += 16) {
            // A fragments: 4 m16-tiles, hi+lo
            uint32_t fa_h[4][4], fa_l[4][4];
            {
                int arow = (lane & 7) + ((lane >> 3) & 1) * 8;
                int acol = ks + ((lane >> 4) << 3);
                #pragma unroll
                for (int mt = 0; mt < 4; mt++) {
                    int r = wm * 64 + mt * 16 + arow;
                    uint32_t ah = smem_u32(sAh + r * LDS_ + acol);
                    uint32_t al = smem_u32(sAl + r * LDS_ + acol);
                    ldsm_x4(fa_h[mt][0], fa_h[mt][1], fa_h[mt][2], fa_h[mt][3], ah);
                    ldsm_x4(fa_l[mt][0], fa_l[mt][1], fa_l[mt][2], fa_l[mt][3], al);
                }
            }
            // B fragments: 4 n8-tiles, hi+lo
            uint32_t fb_h[4][2], fb_l[4][2];
            {
                int brow = lane & 7;
                int bcol = ks + (((lane >> 3) & 1) << 3);
                #pragma unroll
                for (int nt = 0; nt < 4; nt++) {
                    int r = wn * 32 + nt * 8 + brow;
                    uint32_t bh = smem_u32(sBh + r * LDS_ + bcol);
                    uint32_t bl = smem_u32(sBl + r * LDS_ + bcol);
                    ldsm_x2(fb_h[nt][0], fb_h[nt][1], bh);
                    ldsm_x2(fb_l[nt][0], fb_l[nt][1], bl);
                }
            }
            #pragma unroll
            for (int mt = 0; mt < 4; mt++)
                #pragma unroll
                for (int nt = 0; nt < 4; nt++) {
                    mma16816(acc[mt][nt], fa_h[mt], fb_h[nt]);
                    mma16816(acc[mt][nt], fa_l[mt], fb_h[nt]);
                    mma16816(acc[mt][nt], fa_h[mt], fb_l[nt]);
                }
        }
        __syncthreads();
    }

    // epilogue: c0,c1 -> (row lane/4, col 2*(lane%4)); c2,c3 -> row+8
    #pragma unroll
    for (int mt = 0; mt < 4; mt++) {
        #pragma unroll
        for (int nt = 0; nt < 4; nt++) {
            int r0 = row0 + wm * 64 + mt * 16 + (lane >> 2);
            int cc = col0 + wn * 32 + nt * 8 + 2 * (lane & 3);
            if (cc + 1 < N || cc < N) {
                #pragma unroll
                for (int half = 0; half < 2; half++) {
                    int r = r0 + half * 8;
                    if (r >= M) continue;
                    float x0 = acc[mt][nt][half * 2 + 0];
                    float x1 = acc[mt][nt][half * 2 + 1];
                    if (EPI >= 1) {
                        if (cc < N)     x0 += bscale * bias[cc];
                        if (cc + 1 < N) x1 += bscale * bias[cc + 1];
                    }
                    if (EPI == 2) { x0 = tanhf(x0); x1 = tanhf(x1); }
                    if (cc + 1 < N) {
                        *(float2*)(C + (size_t)r * N + cc) = make_float2(x0, x1);
                    } else if (cc < N) {
                        C[(size_t)r * N + cc] = x0;
                    }
                }
            }
        }
    }
}

// ---------------------------------------------------------------------------
// Conversions and elementwise
// ---------------------------------------------------------------------------
__global__ void k_convert(const float* __restrict__ src,
                          __nv_bfloat16* __restrict__ oh,
                          __nv_bfloat16* __restrict__ ol, int total) {
    int i = blockIdx.x * 256 + threadIdx.x;
    if (i >= total) return;
    __nv_bfloat16 h, l;
    split_bf16(src[i], h, l);
    oh[i] = h; ol[i] = l;
}

// transpose + convert: src fp32 [Kr][Nc] -> out [Npad][Kr] bf16 hi/lo (zero pad)
__global__ void k_convt(const float* __restrict__ src,
                        __nv_bfloat16* __restrict__ oh,
                        __nv_bfloat16* __restrict__ ol,
                        int Kr, int Nc, int Npad) {
    __shared__ float t[32][33];
    int n0 = blockIdx.x * 32, k0 = blockIdx.y * 32;
    int tx = threadIdx.x, ty = threadIdx.y;   // 32 x 8
    #pragma unroll
    for (int i = ty; i < 32; i += 8) {
        int k = k0 + i, n = n0 + tx;
        t[i][tx] = (k < Kr && n < Nc) ? src[(size_t)k * Nc + n] : 0.f;
    }
    __syncthreads();
    #pragma unroll
    for (int i = ty; i < 32; i += 8) {
        int n = n0 + i, k = k0 + tx;
        if (n < Npad && k < Kr) {
            __nv_bfloat16 h, l;
            split_bf16(t[tx][i], h, l);
            oh[(size_t)n * Kr + k] = h;
            ol[(size_t)n * Kr + k] = l;
        }
    }
}

__global__ void k_build_wbig_t(const float* __restrict__ Wu,
                               const float* __restrict__ Wb,
                               const float* __restrict__ Wt) {
    int idx = blockIdx.x * 256 + threadIdx.x;
    if (idx >= Nbig * Dh) return;
    int n = idx / Dh;
    int k = idx % Dh;
    int blk = n >> 9, o = n & 511;
    float v;
    switch (blk) {
        case 0:  v = Wu[(size_t)k * Dh + o];                            break;
        case 1:  v = (k >= 256) ? Wb[(size_t)(k - 256) * Dh + o] : 0.f; break;
        case 2:  v = Wb[(size_t)(k + 256) * Dh + o];                    break;
        case 3:  v = (k < 256) ? Wb[(size_t)(k + 768) * Dh + o] : 0.f;  break;
        case 4:  v = Wt[(size_t)k * Dh + o];                            break;
        case 5:  v = Wt[(size_t)(k + 512) * Dh + o];                    break;
        default: v = Wt[(size_t)(k + 1024) * Dh + o];                   break;
    }
    __nv_bfloat16 h, l;
    split_bf16(v, h, l);
    g_wbig_h[idx] = h; g_wbig_l[idx] = l;
}

__global__ void k_sum_image(const float* __restrict__ img) {
    int d = blockIdx.x * 256 + threadIdx.x;
    int b = blockIdx.y;
    const float* p = img + (size_t)b * Rn * Dh + d;
    float s = 0.f;
    #pragma unroll 4
    for (int r = 0; r < Rn; r++) s += p[(size_t)r * Dh];
    g_Simg[b * Dh + d] = s;
}

__global__ void k_gather(const float* __restrict__ emb, const int* __restrict__ q) {
    int m = blockIdx.x;
    int qi = q[m];
    float4 v = ((const float4*)(emb + (size_t)qi * Dh))[threadIdx.x];
    ((float4*)(g_word + (size_t)m * Dh))[threadIdx.x] = v;
    int base = m * Dh + threadIdx.x * 4;
    float xs[4] = {v.x, v.y, v.z, v.w};
    #pragma unroll
    for (int j = 0; j < 4; j++) {
        __nv_bfloat16 h, l;
        split_bf16(xs[j], h, l);
        g_word_h[base + j] = h; g_word_l[base + j] = l;
    }
}

__global__ void k_phrase(const float* __restrict__ b_uni,
                         const float* __restrict__ b_bi,
                         const float* __restrict__ b_tri) {
    int m = blockIdx.x;
    int d = threadIdx.x;
    int t = m % Tn;
    const float* P = g_P7 + (size_t)m * Nbig;
    float uni = P[d]        + b_uni[d];
    float bi  = P[1024 + d] + b_bi[d];
    float tri = P[2560 + d] + b_tri[d];
    if (t > 0) {
        const float* Pm = P - Nbig;
        bi  += Pm[512 + d];
        tri += Pm[2048 + d];
    }
    if (t < Tn - 1) {
        const float* Pp = P + Nbig;
        bi  += Pp[1536 + d];
        tri += Pp[3072 + d];
    }
    float ph = fmaxf(uni, fmaxf(bi, tri));
    g_phrase[(size_t)m * Dh + d] = ph;
    __nv_bfloat16 h, l;
    split_bf16(ph, h, l);
    g_phr_h[(size_t)m * Dh + d] = h;
    g_phr_l[(size_t)m * Dh + d] = l;
}

__global__ void k_zero_state() {
    int i = blockIdx.x * 256 + threadIdx.x;
    if (i < Bn * Dh) { g_hA[i] = 0.f; g_cst[i] = 0.f; g_hsum[i] = 0.f; }
}

__global__ void k_lstm_step(const float* __restrict__ hin,
                            float* __restrict__ hout,
                            const float* __restrict__ Wh, int t) {
    __shared__ float Hs[16][32];
    __shared__ float Ws[16][128];
    const int tid = threadIdx.x;
    const int tx = tid % 16, ty = tid / 16;
    const int d0 = blockIdx.x * 32, b0 = blockIdx.y * 32;

    float acc[2][4][2];
    #pragma unroll
    for (int i = 0; i < 2; i++)
        #pragma unroll
        for (int g = 0; g < 4; g++)
            #pragma unroll
            for (int j = 0; j < 2; j++) acc[i][g][j] = 0.f;

    for (int k0 = 0; k0 < Dh; k0 += 16) {
        #pragma unroll
        for (int it = 0; it < 2; it++) {
            int i = tid + it * 256;
            int bl = i / 16, k = i % 16;
            Hs[k][bl] = hin[(size_t)(b0 + bl) * Dh + k0 + k];
        }
        #pragma unroll
        for (int it = 0; it < 8; it++) {
            int i = tid + it * 256;
            int k = i / 128, c = i % 128;
            int g = c / 32, dl = c % 32;
            Ws[k][c] = Wh[(size_t)(k0 + k) * Ng + g * Dh + d0 + dl];
        }
        __syncthreads();
        #pragma unroll
        for (int k = 0; k < 16; k++) {
            float a0 = Hs[k][ty * 2];
            float a1 = Hs[k][ty * 2 + 1];
            #pragma unroll
            for (int g = 0; g < 4; g++) {
                float w0 = Ws[k][g * 32 + tx * 2];
                float w1 = Ws[k][g * 32 + tx * 2 + 1];
                acc[0][g][0] = fmaf(a0, w0, acc[0][g][0]);
                acc[0][g][1] = fmaf(a0, w1, acc[0][g][1]);
                acc[1][g][0] = fmaf(a1, w0, acc[1][g][0]);
                acc[1][g][1] = fmaf(a1, w1, acc[1][g][1]);
            }
        }
        __syncthreads();
    }

    #pragma unroll
    for (int i = 0; i < 2; i++) {
        int b = b0 + ty * 2 + i;
        size_t xrow = ((size_t)b * Tn + t) * Ng;
        #pragma unroll
        for (int j = 0; j < 2; j++) {
            int d = d0 + tx * 2 + j;
            float gi = acc[i][0][j] + g_xg[xrow + d];
            float gf = acc[i][1][j] + g_xg[xrow + Dh + d];
            float gc = acc[i][2][j] + g_xg[xrow + 2 * Dh + d];
            float go = acc[i][3][j] + g_xg[xrow + 3 * Dh + d];
            size_t bd = (size_t)b * Dh + d;
            float c = sigf(gf) * g_cst[bd] + sigf(gi) * tanhf(gc);
            g_cst[bd] = c;
            float h = sigf(go) * tanhf(c);
            hout[bd] = h;
            g_hsum[bd] += h;
        }
    }
}

// fused: out_h/out_l = split(imgproj[b,d] + sum_t X[b,t,d]); X=nullptr -> use Yvec
__global__ void k_fuse_sum_add_conv(const float* __restrict__ X,
                                    const float* __restrict__ Yvec,
                                    __nv_bfloat16* __restrict__ oh,
                                    __nv_bfloat16* __restrict__ ol,
                                    int stride2) {
    int d = blockIdx.x * 256 + threadIdx.x;
    int b = blockIdx.y;
    float s;
    if (X) {
        s = 0.f;
        #pragma unroll
        for (int t = 0; t < Tn; t++) s += X[((size_t)b * Tn + t) * Dh + d];
    } else {
        s = Yvec[b * Dh + d];
    }
    s += g_imgproj[b * Dh + d];
    __nv_bfloat16 h, l;
    split_bf16(s, h, l);
    oh[(size_t)b * stride2 + d] = h;
    ol[(size_t)b * stride2 + d] = l;
}

// right half of concat from fp32 vec -> bf16 hi/lo at offset Dh
__global__ void k_conv_off(const float* __restrict__ x,
                           __nv_bfloat16* __restrict__ oh,
                           __nv_bfloat16* __restrict__ ol) {
    int i = blockIdx.x * 256 + threadIdx.x;
    if (i >= Bn * Dh) return;
    int b = i / Dh, d = i % Dh;
    __nv_bfloat16 h, l;
    split_bf16(x[i], h, l);
    oh[(size_t)b * 2 * Dh + Dh + d] = h;
    ol[(size_t)b * 2 * Dh + Dh + d] = l;
}

// ---------------------------------------------------------------------------
// Launch
// ---------------------------------------------------------------------------
extern "C" void kernel_launch(void* const* d_in, const int* in_sizes, int n_in,
                              void* d_out, int out_size) {
    const float* image_feat = (const float*)d_in[0];
    const int*   qenc       = (const int*)d_in[1];
    const float* W_ip = (const float*)d_in[2];  const float* b_ip = (const float*)d_in[3];
    const float* emb  = (const float*)d_in[4];
    const float* W_uni = (const float*)d_in[5]; const float* b_uni = (const float*)d_in[6];
    const float* W_bi  = (const float*)d_in[7]; const float* b_bi  = (const float*)d_in[8];
    const float* W_tri = (const float*)d_in[9]; const float* b_tri = (const float*)d_in[10];
    const float* Wx = (const float*)d_in[11];   const float* Wh = (const float*)d_in[12];
    const float* b_lstm = (const float*)d_in[13];
    // d_in[14..23] unused: _pool's softmax over a size-1 axis is identically 1.
    const float* W_w = (const float*)d_in[24];  const float* b_w = (const float*)d_in[25];
    const float* W_p = (const float*)d_in[26];  const float* b_p = (const float*)d_in[27];
    const float* W_s = (const float*)d_in[28];  const float* b_s = (const float*)d_in[29];
    const float* W_f = (const float*)d_in[30];  const float* b_f = (const float*)d_in[31];
    float* out = (float*)d_out;

    // idempotent config (not stream work; safe during capture)
    cudaFuncSetAttribute(gemm_t<0>, cudaFuncAttributeMaxDynamicSharedMemorySize, GEMM_SMEM);
    cudaFuncSetAttribute(gemm_t<1>, cudaFuncAttributeMaxDynamicSharedMemorySize, GEMM_SMEM);
    cudaFuncSetAttribute(gemm_t<2>, cudaFuncAttributeMaxDynamicSharedMemorySize, GEMM_SMEM);

    float *Simg, *imgproj, *word, *P7, *phrase, *xg, *hA, *hB, *hsum, *hw, *hp, *hs;
    __nv_bfloat16 *word_h, *word_l, *phr_h, *phr_l, *wbig_h, *wbig_l;
    __nv_bfloat16 *wx_h, *wx_l, *wip_h, *wip_l, *ww_h, *ww_l;
    __nv_bfloat16 *wp_h, *wp_l, *ws_h, *ws_l, *wf_h, *wf_l;
    __nv_bfloat16 *a512_h, *a512_l, *a1k_h, *a1k_l;

    cudaGetSymbolAddress((void**)&Simg, g_Simg);
    cudaGetSymbolAddress((void**)&imgproj, g_imgproj);
    cudaGetSymbolAddress((void**)&word, g_word);
    cudaGetSymbolAddress((void**)&P7, g_P7);
    cudaGetSymbolAddress((void**)&phrase, g_phrase);
    cudaGetSymbolAddress((void**)&xg, g_xg);
    cudaGetSymbolAddress((void**)&hA, g_hA);
    cudaGetSymbolAddress((void**)&hB, g_hB);
    cudaGetSymbolAddress((void**)&hsum, g_hsum);
    cudaGetSymbolAddress((void**)&hw, g_hw);
    cudaGetSymbolAddress((void**)&hp, g_hp);
    cudaGetSymbolAddress((void**)&hs, g_hs);
    cudaGetSymbolAddress((void**)&word_h, g_word_h);
    cudaGetSymbolAddress((void**)&word_l, g_word_l);
    cudaGetSymbolAddress((void**)&phr_h, g_phr_h);
    cudaGetSymbolAddress((void**)&phr_l, g_phr_l);
    cudaGetSymbolAddress((void**)&wbig_h, g_wbig_h);
    cudaGetSymbolAddress((void**)&wbig_l, g_wbig_l);
    cudaGetSymbolAddress((void**)&wx_h, g_wx_h);
    cudaGetSymbolAddress((void**)&wx_l, g_wx_l);
    cudaGetSymbolAddress((void**)&wip_h, g_wip_h);
    cudaGetSymbolAddress((void**)&wip_l, g_wip_l);
    cudaGetSymbolAddress((void**)&ww_h, g_ww_h);
    cudaGetSymbolAddress((void**)&ww_l, g_ww_l);
    cudaGetSymbolAddress((void**)&wp_h, g_wp_h);
    cudaGetSymbolAddress((void**)&wp_l, g_wp_l);
    cudaGetSymbolAddress((void**)&ws_h, g_ws_h);
    cudaGetSymbolAddress((void**)&ws_l, g_ws_l);
    cudaGetSymbolAddress((void**)&wf_h, g_wf_h);
    cudaGetSymbolAddress((void**)&wf_l, g_wf_l);
    cudaGetSymbolAddress((void**)&a512_h, g_a512_h);
    cudaGetSymbolAddress((void**)&a512_l, g_a512_l);
    cudaGetSymbolAddress((void**)&a1k_h, g_a1k_h);
    cudaGetSymbolAddress((void**)&a1k_l, g_a1k_l);

    dim3 cb(32, 8);

    // --- weight preparation (bf16 hi/lo, transposed to [N][K]) ---
    k_build_wbig_t<<<(Nbig * Dh + 255) / 256, 256>>>(W_uni, W_bi, W_tri);
    k_convt<<<dim3(Ng / 32, Dh / 32), cb>>>(Wx,  wx_h,  wx_l,  Dh, Ng, Ng);
    k_convt<<<dim3(Dh / 32, Dh / 32), cb>>>(W_ip, wip_h, wip_l, Dh, Dh, Dh);
    k_convt<<<dim3(Dh / 32, Dh / 32), cb>>>(W_w,  ww_h,  ww_l,  Dh, Dh, Dh);
    k_convt<<<dim3(Dh / 32, 2 * Dh / 32), cb>>>(W_p, wp_h, wp_l, 2 * Dh, Dh, Dh);
    k_convt<<<dim3(Dh / 32, 2 * Dh / 32), cb>>>(W_s, ws_h, ws_l, 2 * Dh, Dh, Dh);
    k_convt<<<dim3(AVp / 32, Dh / 32), cb>>>(W_f, wf_h, wf_l, Dh, AVn, AVp);

    // --- image sum + projection ---
    k_sum_image<<<dim3(2, Bn), 256>>>(image_feat);
    k_convert<<<(Bn * Dh + 255) / 256, 256>>>(Simg, a512_h, a512_l, Bn * Dh);
    gemm_t<1><<<dim3(Dh / 128, Bn / 128), 256, GEMM_SMEM>>>(
        a512_h, a512_l, wip_h, wip_l, imgproj, b_ip, (float)Rn, Bn, Dh, Dh);

    // --- embeddings, n-gram GEMM, phrase max ---
    k_gather<<<Mw, 128>>>(emb, qenc);
    gemm_t<0><<<dim3(Nbig / 128, Mw / 128), 256, GEMM_SMEM>>>(
        word_h, word_l, wbig_h, wbig_l, P7, nullptr, 0.f, Mw, Nbig, Dh);
    k_phrase<<<Mw, Dh>>>(b_uni, b_bi, b_tri);

    // --- LSTM input projection + recurrence ---
    gemm_t<1><<<dim3(Ng / 128, Mw / 128), 256, GEMM_SMEM>>>(
        phr_h, phr_l, wx_h, wx_l, xg, b_lstm, 1.f, Mw, Ng, Dh);
    k_zero_state<<<(Bn * Dh + 255) / 256, 256>>>();
    for (int t = 0; t < Tn; t++) {
        const float* hi = (t & 1) ? hB : hA;
        float*       ho = (t & 1) ? hA : hB;
        k_lstm_step<<<dim3(Dh / 32, Bn / 32), 256>>>(hi, ho, Wh, t);
    }

    // --- word level: h_w = tanh((imgproj + sum_t word) @ W_w + b_w) ---
    k_fuse_sum_add_conv<<<dim3(2, Bn), 256>>>(word, nullptr, a512_h, a512_l, Dh);
    gemm_t<2><<<dim3(Dh / 128, Bn / 128), 256, GEMM_SMEM>>>(
        a512_h, a512_l, ww_h, ww_l, hw, b_w, 1.f, Bn, Dh, Dh);

    // --- phrase level: h_p = tanh(concat(imgproj + sum_t phrase, h_w) @ W_p + b_p) ---
    k_fuse_sum_add_conv<<<dim3(2, Bn), 256>>>(phrase, nullptr, a1k_h, a1k_l, 2 * Dh);
    k_conv_off<<<(Bn * Dh + 255) / 256, 256>>>(hw, a1k_h, a1k_l);
    gemm_t<2><<<dim3(Dh / 128, Bn / 128), 256, GEMM_SMEM>>>(
        a1k_h, a1k_l, wp_h, wp_l, hp, b_p, 1.f, Bn, Dh, 2 * Dh);

    // --- sentence level: h_s = tanh(concat(imgproj + hsum, h_p) @ W_s + b_s) ---
    k_fuse_sum_add_conv<<<dim3(2, Bn), 256>>>(nullptr, hsum, a1k_h, a1k_l, 2 * Dh);
    k_conv_off<<<(Bn * Dh + 255) / 256, 256>>>(hp, a1k_h, a1k_l);
    gemm_t<2><<<dim3(Dh / 128, Bn / 128), 256, GEMM_SMEM>>>(
        a1k_h, a1k_l, ws_h, ws_l, hs, b_s, 1.f, Bn, Dh, 2 * Dh);

    // --- classifier ---
    k_convert<<<(Bn * Dh + 255) / 256, 256>>>(hs, a512_h, a512_l, Bn * Dh);
    gemm_t<1><<<dim3(AVp / 128, Bn / 128), 256, GEMM_SMEM>>>(
        a512_h, a512_l, wf_h, wf_l, out, b_f, 1.f, Bn, AVn, Dh);
}